// round 13
// baseline (speedup 1.0000x reference)
#include <cuda_runtime.h>

// SpikeLoss: loss = 0.5 * sum( (outputs - psp(target))^2 ), tau = 5
// [32,256,4,4,100] -> 131072 rows x 100 steps, rows contiguous (400B each).
// Persistent grid-stride kernel (R6 structure: 32 regs, ~98% occ): one warp
// per 2 rows per iteration, lanes 0..24 hold one float4 (fully coalesced).
// Kogge-Stone scan with compile-time uniform multipliers, TRUNCATED to 4
// rounds: round-5 multiplier (0.8^4)^16 = 6.3e-7 contributes ~1e-6 relative
// to the loss (tolerance 1e-3) -> dropped. x-loads issued before o-loads
// (o consumed after the scan). Deterministic fused last-block-ticket reduce.

#define T_STEPS   100
#define ROW_V     (T_STEPS / 4)   // 25 float4 per row
#define BLOCK     512
#define WPB       (BLOCK / 32)    // 16 warps -> 32 rows per iteration
#define GRID      592             // 4 blocks/SM on 148 SMs
#define STRIDE    (GRID * WPB)
#define MAX_BLOCKS 1024

__device__ float        g_partials[MAX_BLOCKS];
__device__ unsigned int g_count = 0;

__global__ void __launch_bounds__(BLOCK)
spike_loss_final(const float* __restrict__ outputs,
                 const float* __restrict__ target,
                 float* __restrict__ out,
                 int rows)
{
    const int tid  = threadIdx.x;
    const int lane = tid & 31;
    const int wid  = tid >> 5;

    const float D  = 0.8f;    // decay = 1 - 1/tau
    const float IT = 0.2f;    // 1/tau

    // Kogge-Stone uniform multipliers: (0.8^4)^(2^r), rounds 0..3
    const float C0 = 0.4096f;
    const float C1 = 0.16777216f;
    const float C2 = 2.8147497671e-2f;
    const float C3 = 7.9228162514e-4f;
    // round 4 multiplier 6.28e-7: dropped (error ~1e-6 rel, tol 1e-3)

    const bool lv = (lane < ROW_V);
    const float4* __restrict__ x4 = reinterpret_cast<const float4*>(target);
    const float4* __restrict__ o4 = reinterpret_cast<const float4*>(outputs);

    float acc = 0.0f;
    const int npairs = rows >> 1;                 // 65536 row-pairs

    for (int pair = blockIdx.x * WPB + wid; pair < npairs;
         pair += STRIDE) {

        const size_t ra = (size_t)(2 * pair) * ROW_V + lane;

        float4 xa = make_float4(0.f,0.f,0.f,0.f), oa = xa;
        float4 xb = xa, ob = xa;
        if (lv) {
            // scan-critical x first; o consumed only after the shfl scan
            xa = __ldg(&x4[ra]);
            xb = __ldg(&x4[ra + ROW_V]);
            oa = __ldg(&o4[ra]);
            ob = __ldg(&o4[ra + ROW_V]);
        }

        // Local 4-step scan (zero init): b = syn after this lane's segment.
        float bA = fmaf(D, fmaf(D, fmaf(D, xa.x, xa.y), xa.z), xa.w);
        float bB = fmaf(D, fmaf(D, fmaf(D, xb.x, xb.y), xb.z), xb.w);

        // Kogge-Stone (4 rounds), two independent chains interleaved.
        float pA, pB;
        pA = __shfl_up_sync(0xFFFFFFFFu, bA, 1);
        pB = __shfl_up_sync(0xFFFFFFFFu, bB, 1);
        if (lane >= 1)  { bA = fmaf(C0, pA, bA); bB = fmaf(C0, pB, bB); }
        pA = __shfl_up_sync(0xFFFFFFFFu, bA, 2);
        pB = __shfl_up_sync(0xFFFFFFFFu, bB, 2);
        if (lane >= 2)  { bA = fmaf(C1, pA, bA); bB = fmaf(C1, pB, bB); }
        pA = __shfl_up_sync(0xFFFFFFFFu, bA, 4);
        pB = __shfl_up_sync(0xFFFFFFFFu, bB, 4);
        if (lane >= 4)  { bA = fmaf(C2, pA, bA); bB = fmaf(C2, pB, bB); }
        pA = __shfl_up_sync(0xFFFFFFFFu, bA, 8);
        pB = __shfl_up_sync(0xFFFFFFFFu, bB, 8);
        if (lane >= 8)  { bA = fmaf(C3, pA, bA); bB = fmaf(C3, pB, bB); }

        // Exclusive carry-in.
        float sA = __shfl_up_sync(0xFFFFFFFFu, bA, 1);
        float sB = __shfl_up_sync(0xFFFFFFFFu, bB, 1);
        if (lane == 0) { sA = 0.0f; sB = 0.0f; }

        if (lv) {
            float d;
            sA = fmaf(sA, D, xa.x); d = fmaf(-sA, IT, oa.x); acc = fmaf(d, d, acc);
            sA = fmaf(sA, D, xa.y); d = fmaf(-sA, IT, oa.y); acc = fmaf(d, d, acc);
            sA = fmaf(sA, D, xa.z); d = fmaf(-sA, IT, oa.z); acc = fmaf(d, d, acc);
            sA = fmaf(sA, D, xa.w); d = fmaf(-sA, IT, oa.w); acc = fmaf(d, d, acc);
            sB = fmaf(sB, D, xb.x); d = fmaf(-sB, IT, ob.x); acc = fmaf(d, d, acc);
            sB = fmaf(sB, D, xb.y); d = fmaf(-sB, IT, ob.y); acc = fmaf(d, d, acc);
            sB = fmaf(sB, D, xb.z); d = fmaf(-sB, IT, ob.z); acc = fmaf(d, d, acc);
            sB = fmaf(sB, D, xb.w); d = fmaf(-sB, IT, ob.w); acc = fmaf(d, d, acc);
        }
    }

    // ---- once-per-block deterministic reduction ----
    __shared__ float warp_sums[WPB];
    __shared__ int   is_last;

    #pragma unroll
    for (int off = 16; off > 0; off >>= 1)
        acc += __shfl_down_sync(0xFFFFFFFFu, acc, off);
    if (lane == 0) warp_sums[wid] = acc;
    __syncthreads();

    if (tid == 0) {
        float bsum = 0.0f;
        #pragma unroll
        for (int w = 0; w < WPB; ++w) bsum += warp_sums[w];
        g_partials[blockIdx.x] = bsum;
        __threadfence();
        unsigned int ticket = atomicAdd(&g_count, 1u);
        is_last = (ticket == gridDim.x - 1) ? 1 : 0;
    }
    __syncthreads();

    // ---- last block: fixed-order finalize over GRID partials ----
    if (is_last) {
        const int nblocks = gridDim.x;
        float v = 0.0f;
        for (int i = tid; i < nblocks; i += BLOCK)
            v += g_partials[i];

        #pragma unroll
        for (int off = 16; off > 0; off >>= 1)
            v += __shfl_down_sync(0xFFFFFFFFu, v, off);
        if (lane == 0) warp_sums[wid] = v;
        __syncthreads();

        if (tid == 0) {
            float stot = 0.0f;
            #pragma unroll
            for (int w = 0; w < WPB; ++w) stot += warp_sums[w];
            *out = 0.5f * stot;
            g_count = 0;   // reset for graph replay
        }
    }
}

extern "C" void kernel_launch(void* const* d_in, const int* in_sizes, int n_in,
                              void* d_out, int out_size)
{
    const float* outputs = (const float*)d_in[0];
    const float* target  = (const float*)d_in[1];
    float* out = (float*)d_out;

    const int n    = in_sizes[0];
    const int rows = n / T_STEPS;   // 131072 (even -> pairs exact)

    spike_loss_final<<<GRID, BLOCK>>>(outputs, target, out, rows);
}

// round 14
// speedup vs baseline: 1.3582x; 1.3582x over previous
#include <cuda_runtime.h>

// SpikeLoss: loss = 0.5 * sum( (outputs - psp(target))^2 ), tau = 5
// [32,256,4,4,100] -> 131072 rows x 100 steps, rows contiguous (400B each).
// Persistent grid-stride kernel: one warp processes 2 rows per iteration
// (lanes 0..24 hold one float4 = 4 timesteps each; fully coalesced loads).
// Linear recurrence via Kogge-Stone scan with compile-time uniform
// multipliers ((0.8^4)^(2^r)). No barriers inside the loop; one block
// reduction + deterministic last-block finalize per block (592 total).
// NOTE: this is the exact R6 schedule (17.15us) — empirically the fastest;
// all prefetch/staging/truncation variants regressed against it.

#define T_STEPS   100
#define ROW_V     (T_STEPS / 4)   // 25 float4 per row
#define BLOCK     512
#define WPB       (BLOCK / 32)    // 16 warps -> 32 rows per iteration
#define GRID      592             // ~1 full wave on 148 SMs (4 blocks/SM)
#define MAX_BLOCKS 1024

__device__ float        g_partials[MAX_BLOCKS];
__device__ unsigned int g_count = 0;

__global__ void __launch_bounds__(BLOCK)
spike_loss_persist(const float* __restrict__ outputs,
                   const float* __restrict__ target,
                   float* __restrict__ out,
                   int rows)
{
    const int tid  = threadIdx.x;
    const int lane = tid & 31;
    const int wid  = tid >> 5;

    const float D  = 0.8f;    // decay = 1 - 1/tau
    const float IT = 0.2f;    // 1/tau

    const bool lv = (lane < ROW_V);
    const float4* __restrict__ x4 = reinterpret_cast<const float4*>(target);
    const float4* __restrict__ o4 = reinterpret_cast<const float4*>(outputs);

    // Kogge-Stone uniform multipliers: (0.8^4)^(2^r)
    const float C0 = 0.4096f;
    const float C1 = 0.16777216f;
    const float C2 = 2.8147497671e-2f;
    const float C3 = 7.9228162514e-4f;
    const float C4 = 6.2771017354e-7f;

    float acc = 0.0f;

    const int npairs = rows >> 1;                 // 65536 row-pairs
    // pair index for this warp, grid-strided
    for (int pair = blockIdx.x * WPB + wid; pair < npairs;
         pair += GRID * WPB) {

        const int rowA = pair * 2;
        const int rowB = rowA + 1;

        float4 xa = make_float4(0.f,0.f,0.f,0.f), oa = xa;
        float4 xb = xa, ob = xa;
        if (lv) {
            xa = __ldg(&x4[(size_t)rowA * ROW_V + lane]);
            xb = __ldg(&x4[(size_t)rowB * ROW_V + lane]);
            oa = __ldg(&o4[(size_t)rowA * ROW_V + lane]);
            ob = __ldg(&o4[(size_t)rowB * ROW_V + lane]);
        }

        // Local 4-step scan (zero init): b = syn after this lane's segment.
        float bA = fmaf(D, fmaf(D, fmaf(D, xa.x, xa.y), xa.z), xa.w);
        float bB = fmaf(D, fmaf(D, fmaf(D, xb.x, xb.y), xb.z), xb.w);

        // Kogge-Stone, two independent chains interleaved.
        float pA, pB;
        pA = __shfl_up_sync(0xFFFFFFFFu, bA, 1);
        pB = __shfl_up_sync(0xFFFFFFFFu, bB, 1);
        if (lane >= 1)  { bA = fmaf(C0, pA, bA); bB = fmaf(C0, pB, bB); }
        pA = __shfl_up_sync(0xFFFFFFFFu, bA, 2);
        pB = __shfl_up_sync(0xFFFFFFFFu, bB, 2);
        if (lane >= 2)  { bA = fmaf(C1, pA, bA); bB = fmaf(C1, pB, bB); }
        pA = __shfl_up_sync(0xFFFFFFFFu, bA, 4);
        pB = __shfl_up_sync(0xFFFFFFFFu, bB, 4);
        if (lane >= 4)  { bA = fmaf(C2, pA, bA); bB = fmaf(C2, pB, bB); }
        pA = __shfl_up_sync(0xFFFFFFFFu, bA, 8);
        pB = __shfl_up_sync(0xFFFFFFFFu, bB, 8);
        if (lane >= 8)  { bA = fmaf(C3, pA, bA); bB = fmaf(C3, pB, bB); }
        pA = __shfl_up_sync(0xFFFFFFFFu, bA, 16);
        pB = __shfl_up_sync(0xFFFFFFFFu, bB, 16);
        if (lane >= 16) { bA = fmaf(C4, pA, bA); bB = fmaf(C4, pB, bB); }

        // Exclusive carry-in.
        float sA = __shfl_up_sync(0xFFFFFFFFu, bA, 1);
        float sB = __shfl_up_sync(0xFFFFFFFFu, bB, 1);
        if (lane == 0) { sA = 0.0f; sB = 0.0f; }

        if (lv) {
            float d;
            sA = fmaf(sA, D, xa.x); d = fmaf(-sA, IT, oa.x); acc = fmaf(d, d, acc);
            sA = fmaf(sA, D, xa.y); d = fmaf(-sA, IT, oa.y); acc = fmaf(d, d, acc);
            sA = fmaf(sA, D, xa.z); d = fmaf(-sA, IT, oa.z); acc = fmaf(d, d, acc);
            sA = fmaf(sA, D, xa.w); d = fmaf(-sA, IT, oa.w); acc = fmaf(d, d, acc);
            sB = fmaf(sB, D, xb.x); d = fmaf(-sB, IT, ob.x); acc = fmaf(d, d, acc);
            sB = fmaf(sB, D, xb.y); d = fmaf(-sB, IT, ob.y); acc = fmaf(d, d, acc);
            sB = fmaf(sB, D, xb.z); d = fmaf(-sB, IT, ob.z); acc = fmaf(d, d, acc);
            sB = fmaf(sB, D, xb.w); d = fmaf(-sB, IT, ob.w); acc = fmaf(d, d, acc);
        }
    }

    // ---- once-per-block deterministic reduction ----
    __shared__ float warp_sums[WPB];
    __shared__ int   is_last;

    #pragma unroll
    for (int off = 16; off > 0; off >>= 1)
        acc += __shfl_down_sync(0xFFFFFFFFu, acc, off);
    if (lane == 0) warp_sums[wid] = acc;
    __syncthreads();

    if (tid == 0) {
        float bsum = 0.0f;
        #pragma unroll
        for (int w = 0; w < WPB; ++w) bsum += warp_sums[w];
        g_partials[blockIdx.x] = bsum;
        __threadfence();
        unsigned int ticket = atomicAdd(&g_count, 1u);
        is_last = (ticket == gridDim.x - 1) ? 1 : 0;
    }
    __syncthreads();

    // ---- last block: fixed-order finalize over GRID partials ----
    if (is_last) {
        const int nblocks = gridDim.x;
        float v = 0.0f;
        for (int i = tid; i < nblocks; i += BLOCK)
            v += g_partials[i];

        #pragma unroll
        for (int off = 16; off > 0; off >>= 1)
            v += __shfl_down_sync(0xFFFFFFFFu, v, off);
        if (lane == 0) warp_sums[wid] = v;
        __syncthreads();

        if (tid == 0) {
            float stot = 0.0f;
            #pragma unroll
            for (int w = 0; w < WPB; ++w) stot += warp_sums[w];
            *out = 0.5f * stot;
            g_count = 0;   // reset for graph replay
        }
    }
}

extern "C" void kernel_launch(void* const* d_in, const int* in_sizes, int n_in,
                              void* d_out, int out_size)
{
    const float* outputs = (const float*)d_in[0];
    const float* target  = (const float*)d_in[1];
    float* out = (float*)d_out;

    const int n    = in_sizes[0];
    const int rows = n / T_STEPS;   // 131072 (even -> pairs exact)

    spike_loss_persist<<<GRID, BLOCK>>>(outputs, target, out, rows);
}

// round 15
// speedup vs baseline: 1.3814x; 1.0171x over previous
#include <cuda_runtime.h>

// SpikeLoss: loss = 0.5 * sum( (outputs - psp(target))^2 ), tau = 5
// [32,256,4,4,100] -> 131072 rows x 100 steps, rows contiguous (400B each).
// Persistent grid-stride kernel (exact R6 schedule, 17.15us): one warp per
// 2 rows per iteration, lanes 0..24 hold one float4 (fully coalesced).
// Kogge-Stone scan with compile-time uniform multipliers ((0.8^4)^(2^r)).
// ONLY change vs R6: loads use __ldcg (L2-only, no L1 allocate) — the
// stream has zero L1 reuse, so L1 allocation is pure overhead. Same
// instruction count/schedule, just different cache-op bits.
// Deterministic fused reduction via last-block ticket.

#define T_STEPS   100
#define ROW_V     (T_STEPS / 4)   // 25 float4 per row
#define BLOCK     512
#define WPB       (BLOCK / 32)    // 16 warps -> 32 rows per iteration
#define GRID      592             // ~1 full wave on 148 SMs (4 blocks/SM)
#define MAX_BLOCKS 1024

__device__ float        g_partials[MAX_BLOCKS];
__device__ unsigned int g_count = 0;

__global__ void __launch_bounds__(BLOCK)
spike_loss_persist(const float* __restrict__ outputs,
                   const float* __restrict__ target,
                   float* __restrict__ out,
                   int rows)
{
    const int tid  = threadIdx.x;
    const int lane = tid & 31;
    const int wid  = tid >> 5;

    const float D  = 0.8f;    // decay = 1 - 1/tau
    const float IT = 0.2f;    // 1/tau

    const bool lv = (lane < ROW_V);
    const float4* __restrict__ x4 = reinterpret_cast<const float4*>(target);
    const float4* __restrict__ o4 = reinterpret_cast<const float4*>(outputs);

    // Kogge-Stone uniform multipliers: (0.8^4)^(2^r)
    const float C0 = 0.4096f;
    const float C1 = 0.16777216f;
    const float C2 = 2.8147497671e-2f;
    const float C3 = 7.9228162514e-4f;
    const float C4 = 6.2771017354e-7f;

    float acc = 0.0f;

    const int npairs = rows >> 1;                 // 65536 row-pairs
    for (int pair = blockIdx.x * WPB + wid; pair < npairs;
         pair += GRID * WPB) {

        const int rowA = pair * 2;
        const int rowB = rowA + 1;

        float4 xa = make_float4(0.f,0.f,0.f,0.f), oa = xa;
        float4 xb = xa, ob = xa;
        if (lv) {
            xa = __ldcg(&x4[(size_t)rowA * ROW_V + lane]);
            xb = __ldcg(&x4[(size_t)rowB * ROW_V + lane]);
            oa = __ldcg(&o4[(size_t)rowA * ROW_V + lane]);
            ob = __ldcg(&o4[(size_t)rowB * ROW_V + lane]);
        }

        // Local 4-step scan (zero init): b = syn after this lane's segment.
        float bA = fmaf(D, fmaf(D, fmaf(D, xa.x, xa.y), xa.z), xa.w);
        float bB = fmaf(D, fmaf(D, fmaf(D, xb.x, xb.y), xb.z), xb.w);

        // Kogge-Stone, two independent chains interleaved.
        float pA, pB;
        pA = __shfl_up_sync(0xFFFFFFFFu, bA, 1);
        pB = __shfl_up_sync(0xFFFFFFFFu, bB, 1);
        if (lane >= 1)  { bA = fmaf(C0, pA, bA); bB = fmaf(C0, pB, bB); }
        pA = __shfl_up_sync(0xFFFFFFFFu, bA, 2);
        pB = __shfl_up_sync(0xFFFFFFFFu, bB, 2);
        if (lane >= 2)  { bA = fmaf(C1, pA, bA); bB = fmaf(C1, pB, bB); }
        pA = __shfl_up_sync(0xFFFFFFFFu, bA, 4);
        pB = __shfl_up_sync(0xFFFFFFFFu, bB, 4);
        if (lane >= 4)  { bA = fmaf(C2, pA, bA); bB = fmaf(C2, pB, bB); }
        pA = __shfl_up_sync(0xFFFFFFFFu, bA, 8);
        pB = __shfl_up_sync(0xFFFFFFFFu, bB, 8);
        if (lane >= 8)  { bA = fmaf(C3, pA, bA); bB = fmaf(C3, pB, bB); }
        pA = __shfl_up_sync(0xFFFFFFFFu, bA, 16);
        pB = __shfl_up_sync(0xFFFFFFFFu, bB, 16);
        if (lane >= 16) { bA = fmaf(C4, pA, bA); bB = fmaf(C4, pB, bB); }

        // Exclusive carry-in.
        float sA = __shfl_up_sync(0xFFFFFFFFu, bA, 1);
        float sB = __shfl_up_sync(0xFFFFFFFFu, bB, 1);
        if (lane == 0) { sA = 0.0f; sB = 0.0f; }

        if (lv) {
            float d;
            sA = fmaf(sA, D, xa.x); d = fmaf(-sA, IT, oa.x); acc = fmaf(d, d, acc);
            sA = fmaf(sA, D, xa.y); d = fmaf(-sA, IT, oa.y); acc = fmaf(d, d, acc);
            sA = fmaf(sA, D, xa.z); d = fmaf(-sA, IT, oa.z); acc = fmaf(d, d, acc);
            sA = fmaf(sA, D, xa.w); d = fmaf(-sA, IT, oa.w); acc = fmaf(d, d, acc);
            sB = fmaf(sB, D, xb.x); d = fmaf(-sB, IT, ob.x); acc = fmaf(d, d, acc);
            sB = fmaf(sB, D, xb.y); d = fmaf(-sB, IT, ob.y); acc = fmaf(d, d, acc);
            sB = fmaf(sB, D, xb.z); d = fmaf(-sB, IT, ob.z); acc = fmaf(d, d, acc);
            sB = fmaf(sB, D, xb.w); d = fmaf(-sB, IT, ob.w); acc = fmaf(d, d, acc);
        }
    }

    // ---- once-per-block deterministic reduction ----
    __shared__ float warp_sums[WPB];
    __shared__ int   is_last;

    #pragma unroll
    for (int off = 16; off > 0; off >>= 1)
        acc += __shfl_down_sync(0xFFFFFFFFu, acc, off);
    if (lane == 0) warp_sums[wid] = acc;
    __syncthreads();

    if (tid == 0) {
        float bsum = 0.0f;
        #pragma unroll
        for (int w = 0; w < WPB; ++w) bsum += warp_sums[w];
        g_partials[blockIdx.x] = bsum;
        __threadfence();
        unsigned int ticket = atomicAdd(&g_count, 1u);
        is_last = (ticket == gridDim.x - 1) ? 1 : 0;
    }
    __syncthreads();

    // ---- last block: fixed-order finalize over GRID partials ----
    if (is_last) {
        const int nblocks = gridDim.x;
        float v = 0.0f;
        for (int i = tid; i < nblocks; i += BLOCK)
            v += g_partials[i];

        #pragma unroll
        for (int off = 16; off > 0; off >>= 1)
            v += __shfl_down_sync(0xFFFFFFFFu, v, off);
        if (lane == 0) warp_sums[wid] = v;
        __syncthreads();

        if (tid == 0) {
            float stot = 0.0f;
            #pragma unroll
            for (int w = 0; w < WPB; ++w) stot += warp_sums[w];
            *out = 0.5f * stot;
            g_count = 0;   // reset for graph replay
        }
    }
}

extern "C" void kernel_launch(void* const* d_in, const int* in_sizes, int n_in,
                              void* d_out, int out_size)
{
    const float* outputs = (const float*)d_in[0];
    const float* target  = (const float*)d_in[1];
    float* out = (float*)d_out;

    const int n    = in_sizes[0];
    const int rows = n / T_STEPS;   // 131072 (even -> pairs exact)

    spike_loss_persist<<<GRID, BLOCK>>>(outputs, target, out, rows);
}